// round 1
// baseline (speedup 1.0000x reference)
#include <cuda_runtime.h>
#include <math.h>

#define Nn 256
#define Cc 100
#define Dd 512
#define RW (Nn + Cc)   // 356 total rows (proxies first, then X)

// ---------------- scratch (device globals; no allocation allowed) -------------
__device__ float  g_Xn[Nn * Dd];        // normalized*3 X rows
__device__ float  g_Pn[Cc * Dd];        // normalized*3 proxy rows
__device__ float  g_nsq[RW];            // squared norms of normalized rows (~9)
__device__ float  g_Out[RW * Nn];       // rows 0..99: IPt[c][i]; rows 100..355: G[i][j]
__device__ double g_loss;
__device__ int    g_cnt;

// ---------------- K1: row L2-normalize * SCALE -------------------------------
__global__ void k_norm(const float* __restrict__ X, const float* __restrict__ P) {
    int r   = blockIdx.x;          // 0..355  (r<100: proxy row, else X row r-100)
    int tid = threadIdx.x;         // 128 threads, 4 floats each
    const float4* src;
    float4* dst;
    if (r < Cc) { src = (const float4*)(P + r * Dd);        dst = (float4*)(g_Pn + r * Dd); }
    else        { src = (const float4*)(X + (r - Cc) * Dd); dst = (float4*)(g_Xn + (r - Cc) * Dd); }

    float4 v = src[tid];
    float s = v.x * v.x + v.y * v.y + v.z * v.z + v.w * v.w;
    #pragma unroll
    for (int o = 16; o; o >>= 1) s += __shfl_xor_sync(0xffffffffu, s, o);

    __shared__ float ws[4];
    if ((tid & 31) == 0) ws[tid >> 5] = s;
    __syncthreads();
    float tot = ws[0] + ws[1] + ws[2] + ws[3];

    float inv = 3.0f / fmaxf(sqrtf(tot), 1e-12f);
    v.x *= inv; v.y *= inv; v.z *= inv; v.w *= inv;
    dst[tid] = v;

    if (tid == 0) {
        g_nsq[r] = tot * inv * inv;        // == 9 up to fp rounding
        if (r == 0) { g_loss = 0.0; g_cnt = 0; }
    }
}

// ---------------- K2: Out[r][j] = Wrow_r . Xn_j  (W = [Pn; Xn]) ---------------
// 32x32 tiles, 2x2 per thread, K=512 in 16 chunks of 32.
__global__ void k_gemm() {
    __shared__ float As[32][33];
    __shared__ float Bs[32][33];
    int tid = threadIdx.x;                 // 256
    int tx = tid & 15, ty = tid >> 4;
    int tr = blockIdx.x * 32;              // output row tile (0..383; guard >=356)
    int tc = blockIdx.y * 32;              // output col tile (0..224)

    float a00 = 0.f, a01 = 0.f, a10 = 0.f, a11 = 0.f;

    for (int k0 = 0; k0 < Dd; k0 += 32) {
        #pragma unroll
        for (int i = 0; i < 4; i++) {
            int e  = tid + i * 256;
            int rl = e >> 5, kl = e & 31;
            int rg = tr + rl;
            float av = 0.f;
            if (rg < RW) {
                const float* wrow = (rg < Cc) ? (g_Pn + rg * Dd) : (g_Xn + (rg - Cc) * Dd);
                av = wrow[k0 + kl];
            }
            As[rl][kl] = av;
            Bs[rl][kl] = g_Xn[(tc + rl) * Dd + k0 + kl];
        }
        __syncthreads();
        #pragma unroll
        for (int kk = 0; kk < 32; kk++) {
            float a0 = As[ty][kk],      a1 = As[ty + 16][kk];
            float b0 = Bs[tx][kk],      b1 = Bs[tx + 16][kk];
            a00 = fmaf(a0, b0, a00);    a01 = fmaf(a0, b1, a01);
            a10 = fmaf(a1, b0, a10);    a11 = fmaf(a1, b1, a11);
        }
        __syncthreads();
    }

    int r0 = tr + ty, r1 = tr + ty + 16;
    int c0 = tc + tx, c1 = tc + tx + 16;
    if (r0 < RW) { g_Out[r0 * Nn + c0] = a00; g_Out[r0 * Nn + c1] = a01; }
    if (r1 < RW) { g_Out[r1 * Nn + c0] = a10; g_Out[r1 * Nn + c1] = a11; }
}

// ---------------- K3: real loss (block 0) + pair loss (blocks 1..128) --------
__device__ __forceinline__ float clip1(float x) { return fminf(fmaxf(x, -1.f), 1.f); }

__global__ void k_loss(const int* __restrict__ T) {
    int tid = threadIdx.x;     // 256
    int b   = blockIdx.x;      // 0..128

    __shared__ float shP[Cc];    // pn2[c]
    __shared__ float shB9[Cc];   // 9 + pn2[c]
    __shared__ float shIp1[Cc];  // IPt[c][i1] for current job
    __shared__ float sred[256];
    __shared__ int   sredi[256];

    if (tid < Cc) {
        float p = g_nsq[tid];
        shP[tid]  = p;
        shB9[tid] = 9.0f + p;
    }
    __syncthreads();

    float myLoss = 0.f;
    int   myCnt  = 0;

    if (b == 0) {
        // ---- real-sample loss: one thread per row i ----
        int i = tid;
        float rn = g_nsq[Cc + i];
        int   ti = T[i];
        float s = 0.f;
        #pragma unroll 4
        for (int c = 0; c < Cc; c++) {
            float ip = g_Out[c * Nn + i];                       // coalesced over i
            float d  = fmaxf(fmaf(-2.f, ip, rn + shP[c]), 0.f);
            s += __expf(-d);
        }
        float dT = fmaxf(fmaf(-2.f, g_Out[ti * Nn + i], rn + shP[ti]), 0.f);
        myLoss = dT + __logf(s);
    } else {
        // ---- pair loss: block b handles i1 = b-1 (256-b pairs) and i1 = 256-b (b-1 pairs)
        #pragma unroll 1
        for (int j = 0; j < 2; j++) {
            int i1 = (j == 0) ? (b - 1) : (Nn - b);
            int np = (j == 0) ? (Nn - b) : (b - 1);
            __syncthreads();
            if (tid < Cc) shIp1[tid] = g_Out[tid * Nn + i1];
            __syncthreads();
            if (tid < np) {
                int i2 = i1 + 1 + tid;
                int c1 = T[i1], c2 = T[i2];
                if (c1 != c2) {
                    myCnt++;
                    float x1p1 = clip1(g_Out[c1 * Nn + i1]);
                    float x1p2 = clip1(g_Out[c2 * Nn + i1]);
                    float x2p1 = clip1(g_Out[c1 * Nn + i2]);
                    float x2p2 = clip1(g_Out[c2 * Nn + i2]);
                    float num = x2p2 - x2p1;
                    float den = num + x1p1 - x1p2;
                    float lam = fminf(fmaxf(num / den, 0.3f), 0.7f);
                    float lm  = 1.f - lam;

                    float rnA = g_nsq[Cc + i1];
                    float rnB = g_nsq[Cc + i2];
                    float gg  = g_Out[(Cc + i1) * Nn + i2];     // Xn_i1 . Xn_i2
                    float nw2 = lam * lam * rnA + lm * lm * rnB + 2.f * lam * lm * gg;
                    float t2  = 6.0f / fmaxf(sqrtf(nw2), 1e-12f);   // 2 * SCALE / ||w||

                    float s = 0.f;
                    #pragma unroll 4
                    for (int c = 0; c < Cc; c++) {
                        float ipb = g_Out[c * Nn + i2];          // coalesced over i2
                        float ip  = fmaf(lam, shIp1[c] - ipb, ipb);
                        float d   = fmaxf(fmaf(-t2, ip, shB9[c]), 0.f);
                        s += __expf(-d);
                    }
                    float ipb1 = g_Out[c1 * Nn + i2];
                    float dc1  = fmaxf(fmaf(-t2, fmaf(lam, shIp1[c1] - ipb1, ipb1), shB9[c1]), 0.f);
                    float ipb2 = g_Out[c2 * Nn + i2];
                    float dc2  = fmaxf(fmaf(-t2, fmaf(lam, shIp1[c2] - ipb2, ipb2), shB9[c2]), 0.f);
                    myLoss += lam * dc1 + lm * dc2 + __logf(s);
                }
            }
        }
    }

    // ---- block reduce + atomic accumulate ----
    sred[tid]  = myLoss;
    sredi[tid] = myCnt;
    __syncthreads();
    for (int o = 128; o; o >>= 1) {
        if (tid < o) { sred[tid] += sred[tid + o]; sredi[tid] += sredi[tid + o]; }
        __syncthreads();
    }
    if (tid == 0) {
        atomicAdd(&g_loss, (double)sred[0]);
        atomicAdd(&g_cnt, sredi[0]);
    }
}

// ---------------- K4: finalize ------------------------------------------------
__global__ void k_fin(float* __restrict__ out) {
    out[0] = (float)(g_loss / (double)(Nn + g_cnt));
}

// ---------------- entry -------------------------------------------------------
extern "C" void kernel_launch(void* const* d_in, const int* in_sizes, int n_in,
                              void* d_out, int out_size) {
    const float* X = (const float*)d_in[0];   // [256,512]
    const float* P = (const float*)d_in[1];   // [100,512]
    const int*   T = (const int*)d_in[2];     // [256]
    float* out = (float*)d_out;

    k_norm<<<RW, 128>>>(X, P);
    k_gemm<<<dim3((RW + 31) / 32, Nn / 32), 256>>>();
    k_loss<<<129, 256>>>(T);
    k_fin<<<1, 1>>>(out);
}

// round 2
// speedup vs baseline: 1.0153x; 1.0153x over previous
#include <cuda_runtime.h>
#include <math.h>

#define Nn 256
#define Cc 100
#define Dd 512
#define RW (Nn + Cc)   // 356 rows (proxies first, then X)
#define GB 129         // grid size (<=148 so all CTAs co-resident)

// ---------------- scratch (device globals; no allocation allowed) -------------
__device__ float  g_Xn[Nn * Dd];        // normalized*3 X rows
__device__ float  g_Pn[Cc * Dd];        // normalized*3 proxy rows
__device__ float  g_nsq[RW];            // squared norms of scaled rows (~9)
__device__ float  g_Out[RW * Nn];       // rows 0..99: IPt[c][i]; rows 100..355: G[i][j]
__device__ double g_loss;
__device__ int    g_cnt;
__device__ unsigned g_barCount = 0;     // always returns to 0 after each barrier
__device__ unsigned g_barGen   = 0;     // monotonically increasing generation

// ---------------- software grid barrier (all GB blocks co-resident) ----------
__device__ __forceinline__ void grid_barrier() {
    __syncthreads();
    __threadfence();
    if (threadIdx.x == 0) {
        unsigned oldgen = *(volatile unsigned*)&g_barGen;
        unsigned ticket = atomicAdd(&g_barCount, 1u);
        if (ticket == GB - 1) {
            g_barCount = 0;
            __threadfence();
            atomicExch(&g_barGen, oldgen + 1u);
        } else {
            while (*(volatile unsigned*)&g_barGen == oldgen) { }
        }
        __threadfence();
    }
    __syncthreads();
}

__device__ __forceinline__ float clip1(float x) { return fminf(fmaxf(x, -1.f), 1.f); }

// ---------------- fused kernel ------------------------------------------------
__global__ void __launch_bounds__(256, 1)
k_fused(const float* __restrict__ X, const float* __restrict__ P,
        const int* __restrict__ T, float* __restrict__ out) {
    int tid = threadIdx.x;     // 256
    int b   = blockIdx.x;      // 0..128

    __shared__ float As[32][33];
    __shared__ float Bs[32][33];
    __shared__ float shP[Cc];
    __shared__ float shB9[Cc];
    __shared__ float shIp1[Cc];
    __shared__ float sred[256];
    __shared__ int   sredi[256];
    __shared__ float wsum[8];

    if (b == 0 && tid == 0) { g_loss = 0.0; g_cnt = 0; }

    // ===== Phase 1: row L2-normalize * SCALE ===================================
    for (int r = b; r < RW; r += GB) {
        const float2* src;
        float2* dst;
        if (r < Cc) { src = (const float2*)(P + r * Dd);        dst = (float2*)(g_Pn + r * Dd); }
        else        { src = (const float2*)(X + (r - Cc) * Dd); dst = (float2*)(g_Xn + (r - Cc) * Dd); }

        float2 v = src[tid];
        float s = v.x * v.x + v.y * v.y;
        #pragma unroll
        for (int o = 16; o; o >>= 1) s += __shfl_xor_sync(0xffffffffu, s, o);
        if ((tid & 31) == 0) wsum[tid >> 5] = s;
        __syncthreads();
        float tot = wsum[0] + wsum[1] + wsum[2] + wsum[3]
                  + wsum[4] + wsum[5] + wsum[6] + wsum[7];
        __syncthreads();   // protect wsum before next row iteration

        float inv = 3.0f / fmaxf(sqrtf(tot), 1e-12f);
        v.x *= inv; v.y *= inv;
        dst[tid] = v;
        if (tid == 0) g_nsq[r] = tot * inv * inv;
    }

    grid_barrier();

    // ===== Phase 2: Out[r][j] = Wrow_r . Xn_j  (W = [Pn; Xn]) ==================
    // 96 tiles of 32x32 (12 row-tiles x 8 col-tiles), one per block.
    if (b < 96) {
        int tx = tid & 15, ty = tid >> 4;
        int tr = (b % 12) * 32;
        int tc = (b / 12) * 32;

        float a00 = 0.f, a01 = 0.f, a10 = 0.f, a11 = 0.f;

        for (int k0 = 0; k0 < Dd; k0 += 32) {
            #pragma unroll
            for (int i = 0; i < 4; i++) {
                int e  = tid + i * 256;
                int rl = e >> 5, kl = e & 31;
                int rg = tr + rl;
                float av = 0.f;
                if (rg < RW) {
                    const float* wrow = (rg < Cc) ? (g_Pn + rg * Dd) : (g_Xn + (rg - Cc) * Dd);
                    av = wrow[k0 + kl];
                }
                As[rl][kl] = av;
                Bs[rl][kl] = g_Xn[(tc + rl) * Dd + k0 + kl];
            }
            __syncthreads();
            #pragma unroll
            for (int kk = 0; kk < 32; kk++) {
                float a0 = As[ty][kk],      a1 = As[ty + 16][kk];
                float b0 = Bs[tx][kk],      b1 = Bs[tx + 16][kk];
                a00 = fmaf(a0, b0, a00);    a01 = fmaf(a0, b1, a01);
                a10 = fmaf(a1, b0, a10);    a11 = fmaf(a1, b1, a11);
            }
            __syncthreads();
        }

        int r0 = tr + ty, r1 = tr + ty + 16;
        int c0 = tc + tx, c1 = tc + tx + 16;
        if (r0 < RW) { g_Out[r0 * Nn + c0] = a00; g_Out[r0 * Nn + c1] = a01; }
        if (r1 < RW) { g_Out[r1 * Nn + c0] = a10; g_Out[r1 * Nn + c1] = a11; }
    }

    grid_barrier();

    // ===== Phase 3: real loss (block 0) + pair loss (blocks 1..128) ============
    if (tid < Cc) {
        float p = g_nsq[tid];
        shP[tid]  = p;
        shB9[tid] = 9.0f + p;
    }
    __syncthreads();

    float myLoss = 0.f;
    int   myCnt  = 0;

    if (b == 0) {
        // real-sample loss: one thread per row i
        int i = tid;
        float rn = g_nsq[Cc + i];
        int   ti = T[i];
        float s = 0.f;
        #pragma unroll 4
        for (int c = 0; c < Cc; c++) {
            float ip = g_Out[c * Nn + i];                       // coalesced over i
            float d  = fmaxf(fmaf(-2.f, ip, rn + shP[c]), 0.f);
            s += __expf(-d);
        }
        float dT = fmaxf(fmaf(-2.f, g_Out[ti * Nn + i], rn + shP[ti]), 0.f);
        myLoss = dT + __logf(s);
    } else {
        // pair loss: block b handles i1 = b-1 (256-b pairs) and i1 = 256-b (b-1 pairs)
        #pragma unroll 1
        for (int j = 0; j < 2; j++) {
            int i1 = (j == 0) ? (b - 1) : (Nn - b);
            int np = (j == 0) ? (Nn - b) : (b - 1);
            __syncthreads();
            if (tid < Cc) shIp1[tid] = g_Out[tid * Nn + i1];
            __syncthreads();
            if (tid < np) {
                int i2 = i1 + 1 + tid;
                int c1 = T[i1], c2 = T[i2];
                if (c1 != c2) {
                    myCnt++;
                    float x1p1 = clip1(g_Out[c1 * Nn + i1]);
                    float x1p2 = clip1(g_Out[c2 * Nn + i1]);
                    float x2p1 = clip1(g_Out[c1 * Nn + i2]);
                    float x2p2 = clip1(g_Out[c2 * Nn + i2]);
                    float num = x2p2 - x2p1;
                    float den = num + x1p1 - x1p2;
                    float lam = fminf(fmaxf(num / den, 0.3f), 0.7f);
                    float lm  = 1.f - lam;

                    float rnA = g_nsq[Cc + i1];
                    float rnB = g_nsq[Cc + i2];
                    float gg  = g_Out[(Cc + i1) * Nn + i2];     // Xn_i1 . Xn_i2
                    float nw2 = lam * lam * rnA + lm * lm * rnB + 2.f * lam * lm * gg;
                    float t2  = 6.0f / fmaxf(sqrtf(nw2), 1e-12f);   // 2*SCALE/||w||

                    float s = 0.f;
                    #pragma unroll 4
                    for (int c = 0; c < Cc; c++) {
                        float ipb = g_Out[c * Nn + i2];          // coalesced over i2
                        float ip  = fmaf(lam, shIp1[c] - ipb, ipb);
                        float d   = fmaxf(fmaf(-t2, ip, shB9[c]), 0.f);
                        s += __expf(-d);
                    }
                    float ipb1 = g_Out[c1 * Nn + i2];
                    float dc1  = fmaxf(fmaf(-t2, fmaf(lam, shIp1[c1] - ipb1, ipb1), shB9[c1]), 0.f);
                    float ipb2 = g_Out[c2 * Nn + i2];
                    float dc2  = fmaxf(fmaf(-t2, fmaf(lam, shIp1[c2] - ipb2, ipb2), shB9[c2]), 0.f);
                    myLoss += lam * dc1 + lm * dc2 + __logf(s);
                }
            }
        }
    }

    // block reduce + atomic accumulate
    sred[tid]  = myLoss;
    sredi[tid] = myCnt;
    __syncthreads();
    for (int o = 128; o; o >>= 1) {
        if (tid < o) { sred[tid] += sred[tid + o]; sredi[tid] += sredi[tid + o]; }
        __syncthreads();
    }
    if (tid == 0) {
        atomicAdd(&g_loss, (double)sred[0]);
        atomicAdd(&g_cnt, sredi[0]);
    }

    grid_barrier();

    // ===== Phase 4: finalize ===================================================
    if (b == 0 && tid == 0) {
        out[0] = (float)(g_loss / (double)(Nn + g_cnt));
    }
}

// ---------------- entry -------------------------------------------------------
extern "C" void kernel_launch(void* const* d_in, const int* in_sizes, int n_in,
                              void* d_out, int out_size) {
    const float* X = (const float*)d_in[0];   // [256,512]
    const float* P = (const float*)d_in[1];   // [100,512]
    const int*   T = (const int*)d_in[2];     // [256]
    float* out = (float*)d_out;

    k_fused<<<GB, 256>>>(X, P, T, out);
}

// round 3
// speedup vs baseline: 1.2634x; 1.2443x over previous
#include <cuda_runtime.h>
#include <math.h>

#define Nn 256
#define Cc 100
#define Dd 512
#define RW (Nn + Cc)   // 356 rows (proxies first, then X)
#define GB 129         // grid size (<=148 so all CTAs co-resident)

// ---------------- scratch (device globals; no allocation allowed) -------------
__device__ float  g_Out[RW * Nn];       // rows 0..99: IPt[c][i]; rows 100..355: G[i][j]  (scaled)
__device__ double g_loss;
__device__ int    g_cnt;
__device__ unsigned g_barCount = 0;     // returns to 0 after each barrier
__device__ unsigned g_barGen   = 0;     // monotonic generation
__device__ unsigned g_done     = 0;     // finalize ticket (reset by last block)

// ---------------- software grid barrier (all GB blocks co-resident) ----------
__device__ __forceinline__ void grid_barrier() {
    __syncthreads();
    __threadfence();
    if (threadIdx.x == 0) {
        unsigned oldgen = *(volatile unsigned*)&g_barGen;
        unsigned ticket = atomicAdd(&g_barCount, 1u);
        if (ticket == GB - 1) {
            g_barCount = 0;
            __threadfence();
            atomicExch(&g_barGen, oldgen + 1u);
        } else {
            while (*(volatile unsigned*)&g_barGen == oldgen) { }
        }
        __threadfence();
    }
    __syncthreads();
}

__device__ __forceinline__ float clip1(float x) { return fminf(fmaxf(x, -1.f), 1.f); }

// ---------------- fused kernel ------------------------------------------------
__global__ void __launch_bounds__(256, 1)
k_fused(const float* __restrict__ X, const float* __restrict__ P,
        const int* __restrict__ T, float* __restrict__ out) {
    int tid  = threadIdx.x;    // 256
    int b    = blockIdx.x;     // 0..128
    int lane = tid & 31;
    int wid  = tid >> 5;       // 0..7

    __shared__ float As[32][34];     // transposed: As[kk][row], pitch 34 (8B-aligned pairs)
    __shared__ float Bs[32][34];
    __shared__ float rinvA[32];      // 1/max(||row||,eps) for A-tile rows
    __shared__ float rinvB[32];      // for B-tile rows (X cols)
    __shared__ float shIp1[Cc];
    __shared__ float sred[256];
    __shared__ int   sredi[256];

    if (b == 0 && tid == 0) { g_loss = 0.0; g_cnt = 0; }

    // ===== Phase 1: GEMM on RAW inputs (96 blocks), epilogue scales by 9*rinv ==
    // Out[r][j] = 9 * (W_r . X_j) / (max(||W_r||,eps) * max(||X_j||,eps))
    if (b < 96) {
        int tr = (b % 12) * 32;        // A row tile (W = [P; X])
        int tc = (b / 12) * 32;        // B row tile (X cols)

        // --- per-tile row norms: 8 warps x 8 rows each (reads warm L1 for GEMM)
        for (int m = wid; m < 64; m += 8) {
            const float* rp;
            bool valid = true;
            if (m < 32) {
                int g = tr + m;
                if (g >= RW) valid = false;
                rp = (g < Cc) ? (P + g * Dd) : (X + (g - Cc) * Dd);
            } else {
                rp = X + (tc + (m - 32)) * Dd;
            }
            float s = 0.f;
            if (valid) {
                const float4* rp4 = (const float4*)rp;
                #pragma unroll
                for (int q = 0; q < 4; q++) {
                    float4 v = rp4[lane + 32 * q];
                    s += v.x * v.x + v.y * v.y + v.z * v.z + v.w * v.w;
                }
            }
            #pragma unroll
            for (int o = 16; o; o >>= 1) s += __shfl_xor_sync(0xffffffffu, s, o);
            if (lane == 0) {
                float ri = valid ? (1.0f / fmaxf(sqrtf(s), 1e-12f)) : 0.f;
                if (m < 32) rinvA[m] = ri; else rinvB[m - 32] = ri;
            }
        }
        __syncthreads();

        // --- main loop: 16 K-chunks of 32, register-prefetch double buffered
        int tx = tid & 15, ty = tid >> 4;
        int rl = tid >> 5, kl = tid & 31;       // load coords (4 elems each, rl+=8)
        float a00 = 0.f, a01 = 0.f, a10 = 0.f, a11 = 0.f;
        float pa[4], pb[4];

        // prefetch chunk 0
        #pragma unroll
        for (int i = 0; i < 4; i++) {
            int r = rl + i * 8;
            int ga = tr + r;
            float av = 0.f;
            if (ga < RW) {
                const float* wrow = (ga < Cc) ? (P + ga * Dd) : (X + (ga - Cc) * Dd);
                av = wrow[kl];
            }
            pa[i] = av;
            pb[i] = X[(tc + r) * Dd + kl];
        }

        for (int ch = 0; ch < 16; ch++) {
            // store prefetched chunk to smem (transposed)
            #pragma unroll
            for (int i = 0; i < 4; i++) {
                int r = rl + i * 8;
                As[kl][r] = pa[i];
                Bs[kl][r] = pb[i];
            }
            __syncthreads();

            // prefetch next chunk
            if (ch < 15) {
                int k0 = (ch + 1) * 32;
                #pragma unroll
                for (int i = 0; i < 4; i++) {
                    int r = rl + i * 8;
                    int ga = tr + r;
                    float av = 0.f;
                    if (ga < RW) {
                        const float* wrow = (ga < Cc) ? (P + ga * Dd) : (X + (ga - Cc) * Dd);
                        av = wrow[k0 + kl];
                    }
                    pa[i] = av;
                    pb[i] = X[(tc + r) * Dd + k0 + kl];
                }
            }

            // compute
            #pragma unroll
            for (int kk = 0; kk < 32; kk++) {
                float2 a = *(const float2*)&As[kk][2 * ty];
                float2 v = *(const float2*)&Bs[kk][2 * tx];
                a00 = fmaf(a.x, v.x, a00);  a01 = fmaf(a.x, v.y, a01);
                a10 = fmaf(a.y, v.x, a10);  a11 = fmaf(a.y, v.y, a11);
            }
            __syncthreads();
        }

        // --- epilogue: scale + store
        float riA0 = 9.0f * rinvA[2 * ty];
        float riA1 = 9.0f * rinvA[2 * ty + 1];
        float riB0 = rinvB[2 * tx];
        float riB1 = rinvB[2 * tx + 1];
        int r0 = tr + 2 * ty, r1 = r0 + 1;
        int c0 = tc + 2 * tx;
        if (r0 < RW) {
            float2 o0 = make_float2(a00 * riA0 * riB0, a01 * riA0 * riB1);
            *(float2*)&g_Out[r0 * Nn + c0] = o0;
        }
        if (r1 < RW) {
            float2 o1 = make_float2(a10 * riA1 * riB0, a11 * riA1 * riB1);
            *(float2*)&g_Out[r1 * Nn + c0] = o1;
        }
    }

    grid_barrier();

    // ===== Phase 2: losses. All norms^2 == 9 exactly; bias = 18 =================
    float myLoss = 0.f;
    int   myCnt  = 0;

    if (b == 0) {
        // real-sample loss: one thread per row i
        int i = tid;
        int ti = T[i];
        float s = 0.f;
        #pragma unroll 4
        for (int c = 0; c < Cc; c++) {
            float ip = g_Out[c * Nn + i];                       // coalesced over i
            float d  = fmaxf(fmaf(-2.f, ip, 18.0f), 0.f);
            s += __expf(-d);
        }
        float dT = fmaxf(fmaf(-2.f, g_Out[ti * Nn + i], 18.0f), 0.f);
        myLoss = dT + __logf(s);
    } else {
        // pair loss: block b handles i1 = b-1 (256-b pairs) and i1 = 256-b (b-1 pairs)
        #pragma unroll 1
        for (int j = 0; j < 2; j++) {
            int i1 = (j == 0) ? (b - 1) : (Nn - b);
            int np = (j == 0) ? (Nn - b) : (b - 1);
            __syncthreads();
            if (tid < Cc) shIp1[tid] = g_Out[tid * Nn + i1];
            __syncthreads();
            if (tid < np) {
                int i2 = i1 + 1 + tid;
                int c1 = T[i1], c2 = T[i2];
                if (c1 != c2) {
                    myCnt++;
                    float x1p1 = clip1(shIp1[c1]);
                    float x1p2 = clip1(shIp1[c2]);
                    float x2p1 = clip1(g_Out[c1 * Nn + i2]);
                    float x2p2 = clip1(g_Out[c2 * Nn + i2]);
                    float num = x2p2 - x2p1;
                    float den = num + x1p1 - x1p2;
                    float lam = fminf(fmaxf(num / den, 0.3f), 0.7f);
                    float lm  = 1.f - lam;

                    float gg  = g_Out[(Cc + i1) * Nn + i2];     // Xn_i1 . Xn_i2
                    float nw2 = 9.0f * (lam * lam + lm * lm) + 2.f * lam * lm * gg;
                    float t2  = 6.0f / fmaxf(sqrtf(nw2), 1e-12f);   // 2*SCALE/||virt||

                    float s = 0.f;
                    #pragma unroll 4
                    for (int c = 0; c < Cc; c++) {
                        float ipb = g_Out[c * Nn + i2];          // coalesced over i2
                        float ip  = fmaf(lam, shIp1[c] - ipb, ipb);
                        float d   = fmaxf(fmaf(-t2, ip, 18.0f), 0.f);
                        s += __expf(-d);
                    }
                    float ipb1 = g_Out[c1 * Nn + i2];
                    float dc1  = fmaxf(fmaf(-t2, fmaf(lam, shIp1[c1] - ipb1, ipb1), 18.0f), 0.f);
                    float ipb2 = g_Out[c2 * Nn + i2];
                    float dc2  = fmaxf(fmaf(-t2, fmaf(lam, shIp1[c2] - ipb2, ipb2), 18.0f), 0.f);
                    myLoss += lam * dc1 + lm * dc2 + __logf(s);
                }
            }
        }
    }

    // block reduce
    sred[tid]  = myLoss;
    sredi[tid] = myCnt;
    __syncthreads();
    for (int o = 128; o; o >>= 1) {
        if (tid < o) { sred[tid] += sred[tid + o]; sredi[tid] += sredi[tid + o]; }
        __syncthreads();
    }

    // ===== Phase 3: accumulate + last-block finalize (no grid barrier) =========
    if (tid == 0) {
        atomicAdd(&g_loss, (double)sred[0]);
        atomicAdd(&g_cnt, sredi[0]);
        __threadfence();
        unsigned t = atomicAdd(&g_done, 1u);
        if (t == GB - 1) {
            double L = atomicAdd(&g_loss, 0.0);   // L2-coherent read
            int    C = atomicAdd(&g_cnt, 0);
            out[0] = (float)(L / (double)(Nn + C));
            __threadfence();
            atomicExch(&g_done, 0u);              // reset for graph replay
        }
    }
}

// ---------------- entry -------------------------------------------------------
extern "C" void kernel_launch(void* const* d_in, const int* in_sizes, int n_in,
                              void* d_out, int out_size) {
    const float* X = (const float*)d_in[0];   // [256,512]
    const float* P = (const float*)d_in[1];   // [100,512]
    const int*   T = (const int*)d_in[2];     // [256]
    float* out = (float*)d_out;

    k_fused<<<GB, 256>>>(X, P, T, out);
}

// round 4
// speedup vs baseline: 1.2917x; 1.0224x over previous
#include <cuda_runtime.h>
#include <math.h>

#define Nn 256
#define Cc 100
#define Dd 512
#define RW (Nn + Cc)   // 356 rows (proxies first, then X)
#define GB 256         // grid size; 2 CTAs/SM co-resident (256 <= 148*2)

// ---------------- scratch (device globals; no allocation allowed) -------------
__device__ float  g_Out0[RW * Nn];      // K-half 0 partial (scaled)
__device__ float  g_Out1[RW * Nn];      // K-half 1 partial (scaled)
__device__ double g_loss;
__device__ int    g_cnt;
__device__ unsigned g_barCount = 0;     // returns to 0 after each barrier
__device__ unsigned g_barGen   = 0;     // monotonic generation
__device__ unsigned g_done     = 0;     // finalize ticket (reset by last block)

// ---------------- software grid barrier (all GB blocks co-resident) ----------
__device__ __forceinline__ void grid_barrier() {
    __syncthreads();
    __threadfence();
    if (threadIdx.x == 0) {
        unsigned oldgen = *(volatile unsigned*)&g_barGen;
        unsigned ticket = atomicAdd(&g_barCount, 1u);
        if (ticket == GB - 1) {
            g_barCount = 0;
            __threadfence();
            atomicExch(&g_barGen, oldgen + 1u);
        } else {
            while (*(volatile unsigned*)&g_barGen == oldgen) { }
        }
        __threadfence();
    }
    __syncthreads();
}

__device__ __forceinline__ float clip1(float x) { return fminf(fmaxf(x, -1.f), 1.f); }

// ---------------- fused kernel ------------------------------------------------
__global__ void __launch_bounds__(256, 2)
k_fused(const float* __restrict__ X, const float* __restrict__ P,
        const int* __restrict__ T, float* __restrict__ out) {
    int tid  = threadIdx.x;    // 256
    int b    = blockIdx.x;     // 0..255
    int lane = tid & 31;
    int wid  = tid >> 5;       // 0..7

    __shared__ float As[32][34];     // transposed: As[kk][row]
    __shared__ float Bs[32][34];
    __shared__ float rinvA[32];
    __shared__ float rinvB[32];
    __shared__ float shIp1[Cc];
    __shared__ float sred[256];
    __shared__ int   sredi[256];

    if (b == 0 && tid == 0) { g_loss = 0.0; g_cnt = 0; }

    // ===== Phase 1: split-K GEMM on RAW inputs (192 blocks: 96 tiles x 2 halves)
    // OutH[r][j] = 9 * (W_r[Kh] . X_j[Kh]) / (||W_r|| * ||X_j||), W = [P; X]
    if (b < 192) {
        int h  = b & 1;                // K half
        int t  = b >> 1;               // tile 0..95
        int tr = (t % 12) * 32;        // A row tile
        int tc = (t / 12) * 32;        // B row tile (X cols)
        int kb = h * 256;              // K base

        // --- per-tile FULL row norms (8 warps x 8 rows)
        for (int m = wid; m < 64; m += 8) {
            const float* rp;
            bool valid = true;
            if (m < 32) {
                int g = tr + m;
                if (g >= RW) valid = false;
                rp = (g < Cc) ? (P + g * Dd) : (X + (g - Cc) * Dd);
            } else {
                rp = X + (tc + (m - 32)) * Dd;
            }
            float s = 0.f;
            if (valid) {
                const float4* rp4 = (const float4*)rp;
                #pragma unroll
                for (int q = 0; q < 4; q++) {
                    float4 v = rp4[lane + 32 * q];
                    s += v.x * v.x + v.y * v.y + v.z * v.z + v.w * v.w;
                }
            }
            #pragma unroll
            for (int o = 16; o; o >>= 1) s += __shfl_xor_sync(0xffffffffu, s, o);
            if (lane == 0) {
                float ri = valid ? (1.0f / fmaxf(sqrtf(s), 1e-12f)) : 0.f;
                if (m < 32) rinvA[m] = ri; else rinvB[m - 32] = ri;
            }
        }
        __syncthreads();

        // --- main loop: 8 K-chunks of 32, register-prefetch double buffered
        int tx = tid & 15, ty = tid >> 4;
        int rl = tid >> 5, kl = tid & 31;
        float a00 = 0.f, a01 = 0.f, a10 = 0.f, a11 = 0.f;
        float pa[4], pb[4];

        #pragma unroll
        for (int i = 0; i < 4; i++) {
            int r = rl + i * 8;
            int ga = tr + r;
            float av = 0.f;
            if (ga < RW) {
                const float* wrow = (ga < Cc) ? (P + ga * Dd) : (X + (ga - Cc) * Dd);
                av = wrow[kb + kl];
            }
            pa[i] = av;
            pb[i] = X[(tc + r) * Dd + kb + kl];
        }

        for (int ch = 0; ch < 8; ch++) {
            #pragma unroll
            for (int i = 0; i < 4; i++) {
                int r = rl + i * 8;
                As[kl][r] = pa[i];
                Bs[kl][r] = pb[i];
            }
            __syncthreads();

            if (ch < 7) {
                int k0 = kb + (ch + 1) * 32;
                #pragma unroll
                for (int i = 0; i < 4; i++) {
                    int r = rl + i * 8;
                    int ga = tr + r;
                    float av = 0.f;
                    if (ga < RW) {
                        const float* wrow = (ga < Cc) ? (P + ga * Dd) : (X + (ga - Cc) * Dd);
                        av = wrow[k0 + kl];
                    }
                    pa[i] = av;
                    pb[i] = X[(tc + r) * Dd + k0 + kl];
                }
            }

            #pragma unroll
            for (int kk = 0; kk < 32; kk++) {
                float2 a = *(const float2*)&As[kk][2 * ty];
                float2 v = *(const float2*)&Bs[kk][2 * tx];
                a00 = fmaf(a.x, v.x, a00);  a01 = fmaf(a.x, v.y, a01);
                a10 = fmaf(a.y, v.x, a10);  a11 = fmaf(a.y, v.y, a11);
            }
            __syncthreads();
        }

        // --- epilogue: scale + store into half-buffer
        float* Oh = h ? g_Out1 : g_Out0;
        float riA0 = 9.0f * rinvA[2 * ty];
        float riA1 = 9.0f * rinvA[2 * ty + 1];
        float riB0 = rinvB[2 * tx];
        float riB1 = rinvB[2 * tx + 1];
        int r0 = tr + 2 * ty, r1 = r0 + 1;
        int c0 = tc + 2 * tx;
        if (r0 < RW) {
            *(float2*)&Oh[r0 * Nn + c0] =
                make_float2(a00 * riA0 * riB0, a01 * riA0 * riB1);
        }
        if (r1 < RW) {
            *(float2*)&Oh[r1 * Nn + c0] =
                make_float2(a10 * riA1 * riB0, a11 * riA1 * riB1);
        }
    }

    grid_barrier();

    // ===== Phase 2: losses. All scaled norms^2 == 9; bias = 18 =================
    float myLoss = 0.f;
    int   myCnt  = 0;

    if (b == 0) {
        // real-sample loss: one thread per row i
        int i = tid;
        int ti = T[i];
        float s = 0.f;
        #pragma unroll 4
        for (int c = 0; c < Cc; c++) {
            float ip = g_Out0[c * Nn + i] + g_Out1[c * Nn + i];   // coalesced over i
            float d  = fmaxf(fmaf(-2.f, ip, 18.0f), 0.f);
            s += __expf(-d);
        }
        float ipT = g_Out0[ti * Nn + i] + g_Out1[ti * Nn + i];
        float dT  = fmaxf(fmaf(-2.f, ipT, 18.0f), 0.f);
        myLoss = dT + __logf(s);
    } else {
        // pair loss: block b handles i1 = b-1, pairs i2 = i1+1..255 (one pass)
        int i1 = b - 1;                 // 0..254
        int np = Nn - 1 - i1;           // 255..1
        if (tid < Cc) shIp1[tid] = g_Out0[tid * Nn + i1] + g_Out1[tid * Nn + i1];
        __syncthreads();
        if (tid < np) {
            int i2 = i1 + 1 + tid;
            int c1 = T[i1], c2 = T[i2];
            if (c1 != c2) {
                myCnt = 1;
                float x2p1i = g_Out0[c1 * Nn + i2] + g_Out1[c1 * Nn + i2];
                float x2p2i = g_Out0[c2 * Nn + i2] + g_Out1[c2 * Nn + i2];
                float x1p1 = clip1(shIp1[c1]);
                float x1p2 = clip1(shIp1[c2]);
                float x2p1 = clip1(x2p1i);
                float x2p2 = clip1(x2p2i);
                float num = x2p2 - x2p1;
                float den = num + x1p1 - x1p2;
                float lam = fminf(fmaxf(num / den, 0.3f), 0.7f);
                float lm  = 1.f - lam;

                float gg  = g_Out0[(Cc + i1) * Nn + i2] + g_Out1[(Cc + i1) * Nn + i2];
                float nw2 = 9.0f * (lam * lam + lm * lm) + 2.f * lam * lm * gg;
                float t2  = 6.0f / fmaxf(sqrtf(nw2), 1e-12f);   // 2*SCALE/||virt||

                float s = 0.f;
                #pragma unroll 4
                for (int c = 0; c < Cc; c++) {
                    float ipb = g_Out0[c * Nn + i2] + g_Out1[c * Nn + i2];
                    float ip  = fmaf(lam, shIp1[c] - ipb, ipb);
                    float d   = fmaxf(fmaf(-t2, ip, 18.0f), 0.f);
                    s += __expf(-d);
                }
                float dc1 = fmaxf(fmaf(-t2, fmaf(lam, shIp1[c1] - x2p1i, x2p1i), 18.0f), 0.f);
                float dc2 = fmaxf(fmaf(-t2, fmaf(lam, shIp1[c2] - x2p2i, x2p2i), 18.0f), 0.f);
                myLoss = lam * dc1 + lm * dc2 + __logf(s);
            }
        }
    }

    // block reduce
    sred[tid]  = myLoss;
    sredi[tid] = myCnt;
    __syncthreads();
    for (int o = 128; o; o >>= 1) {
        if (tid < o) { sred[tid] += sred[tid + o]; sredi[tid] += sredi[tid + o]; }
        __syncthreads();
    }

    // ===== Phase 3: accumulate + last-block finalize (no grid barrier) =========
    if (tid == 0) {
        atomicAdd(&g_loss, (double)sred[0]);
        atomicAdd(&g_cnt, sredi[0]);
        __threadfence();
        unsigned t = atomicAdd(&g_done, 1u);
        if (t == GB - 1) {
            double L = atomicAdd(&g_loss, 0.0);   // coherent read
            int    C = atomicAdd(&g_cnt, 0);
            out[0] = (float)(L / (double)(Nn + C));
            __threadfence();
            atomicExch(&g_done, 0u);              // reset for graph replay
        }
    }
}

// ---------------- entry -------------------------------------------------------
extern "C" void kernel_launch(void* const* d_in, const int* in_sizes, int n_in,
                              void* d_out, int out_size) {
    const float* X = (const float*)d_in[0];   // [256,512]
    const float* P = (const float*)d_in[1];   // [100,512]
    const int*   T = (const int*)d_in[2];     // [256]
    float* out = (float*)d_out;

    k_fused<<<GB, 256>>>(X, P, T, out);
}

// round 5
// speedup vs baseline: 1.4518x; 1.1239x over previous
#include <cuda_runtime.h>
#include <math.h>

#define Nn 256
#define Cc 100
#define Dd 512
#define RW (Nn + Cc)   // 356 rows (proxies first, then X)
#define GB 256         // grid; 2 CTAs/SM co-resident (256 <= 296 capacity)

#define LOG2E 1.442695040888963f

// ---------------- scratch (device globals; no allocation allowed) -------------
__device__ float  g_Out[RW * Nn];       // rows 0..99: IPt[c][i]; rows 100..355: G[i][j]
__device__ float  g_partF[GB];
__device__ int    g_partI[GB];
__device__ unsigned g_barCount = 0;     // returns to 0 after each barrier
__device__ unsigned g_barGen   = 0;     // monotonic generation
__device__ unsigned g_done     = 0;     // finalize ticket (reset by last block)

__device__ __forceinline__ float ex2f(float x) {
    float r; asm("ex2.approx.ftz.f32 %0, %1;" : "=f"(r) : "f"(x)); return r;
}

// ---------------- software grid barrier (all GB blocks co-resident) ----------
__device__ __forceinline__ void grid_barrier() {
    __syncthreads();
    __threadfence();
    if (threadIdx.x == 0) {
        unsigned oldgen = *(volatile unsigned*)&g_barGen;
        unsigned ticket = atomicAdd(&g_barCount, 1u);
        if (ticket == GB - 1) {
            g_barCount = 0;
            __threadfence();
            atomicExch(&g_barGen, oldgen + 1u);
        } else {
            while (*(volatile unsigned*)&g_barGen == oldgen) { __nanosleep(64); }
        }
        __threadfence();
    }
    __syncthreads();
}

__device__ __forceinline__ float clip1(float x) { return fminf(fmaxf(x, -1.f), 1.f); }

// ---------------- fused kernel ------------------------------------------------
__global__ void __launch_bounds__(256, 2)
k_fused(const float* __restrict__ X, const float* __restrict__ P,
        const int* __restrict__ T, float* __restrict__ out) {
    int tid  = threadIdx.x;    // 256
    int b    = blockIdx.x;     // 0..255
    int lane = tid & 31;
    int wid  = tid >> 5;       // 0..7

    __shared__ float As[32][34];     // transposed: As[kk][row]
    __shared__ float Bs[32][34];
    __shared__ float rinvA[32];
    __shared__ float rinvB[32];
    __shared__ float shIp1[Cc];
    __shared__ float sred[256];
    __shared__ int   sredi[256];
    __shared__ int   lastFlag;

    // ===== Phase 1: GEMM on RAW inputs (96 blocks of 32x32 tile, K=512) ========
    // Out[r][j] = 9 * (W_r . X_j) / (||W_r|| * ||X_j||), W = [P; X]
    if (b < 96) {
        int tr = (b % 12) * 32;        // A row tile
        int tc = (b / 12) * 32;        // B row tile (X cols)

        // --- per-tile row norms (8 warps x 8 rows)
        for (int m = wid; m < 64; m += 8) {
            const float* rp;
            bool valid = true;
            if (m < 32) {
                int g = tr + m;
                if (g >= RW) valid = false;
                rp = (g < Cc) ? (P + g * Dd) : (X + (g - Cc) * Dd);
            } else {
                rp = X + (tc + (m - 32)) * Dd;
            }
            float s = 0.f;
            if (valid) {
                const float4* rp4 = (const float4*)rp;
                #pragma unroll
                for (int q = 0; q < 4; q++) {
                    float4 v = rp4[lane + 32 * q];
                    s += v.x * v.x + v.y * v.y + v.z * v.z + v.w * v.w;
                }
            }
            #pragma unroll
            for (int o = 16; o; o >>= 1) s += __shfl_xor_sync(0xffffffffu, s, o);
            if (lane == 0) {
                float ri = valid ? (1.0f / fmaxf(sqrtf(s), 1e-12f)) : 0.f;
                if (m < 32) rinvA[m] = ri; else rinvB[m - 32] = ri;
            }
        }
        __syncthreads();

        // --- main loop: 16 K-chunks of 32, register-prefetch double buffered
        int tx = tid & 15, ty = tid >> 4;
        int rl = tid >> 5, kl = tid & 31;
        float a00 = 0.f, a01 = 0.f, a10 = 0.f, a11 = 0.f;
        float pa[4], pb[4];

        #pragma unroll
        for (int i = 0; i < 4; i++) {
            int r = rl + i * 8;
            int ga = tr + r;
            float av = 0.f;
            if (ga < RW) {
                const float* wrow = (ga < Cc) ? (P + ga * Dd) : (X + (ga - Cc) * Dd);
                av = wrow[kl];
            }
            pa[i] = av;
            pb[i] = X[(tc + r) * Dd + kl];
        }

        for (int ch = 0; ch < 16; ch++) {
            #pragma unroll
            for (int i = 0; i < 4; i++) {
                int r = rl + i * 8;
                As[kl][r] = pa[i];
                Bs[kl][r] = pb[i];
            }
            __syncthreads();

            if (ch < 15) {
                int k0 = (ch + 1) * 32;
                #pragma unroll
                for (int i = 0; i < 4; i++) {
                    int r = rl + i * 8;
                    int ga = tr + r;
                    float av = 0.f;
                    if (ga < RW) {
                        const float* wrow = (ga < Cc) ? (P + ga * Dd) : (X + (ga - Cc) * Dd);
                        av = wrow[k0 + kl];
                    }
                    pa[i] = av;
                    pb[i] = X[(tc + r) * Dd + k0 + kl];
                }
            }

            #pragma unroll
            for (int kk = 0; kk < 32; kk++) {
                float2 a = *(const float2*)&As[kk][2 * ty];
                float2 v = *(const float2*)&Bs[kk][2 * tx];
                a00 = fmaf(a.x, v.x, a00);  a01 = fmaf(a.x, v.y, a01);
                a10 = fmaf(a.y, v.x, a10);  a11 = fmaf(a.y, v.y, a11);
            }
            __syncthreads();
        }

        // --- epilogue: scale + store
        float riA0 = 9.0f * rinvA[2 * ty];
        float riA1 = 9.0f * rinvA[2 * ty + 1];
        float riB0 = rinvB[2 * tx];
        float riB1 = rinvB[2 * tx + 1];
        int r0 = tr + 2 * ty, r1 = r0 + 1;
        int c0 = tc + 2 * tx;
        if (r0 < RW)
            *(float2*)&g_Out[r0 * Nn + c0] = make_float2(a00 * riA0 * riB0, a01 * riA0 * riB1);
        if (r1 < RW)
            *(float2*)&g_Out[r1 * Nn + c0] = make_float2(a10 * riA1 * riB0, a11 * riA1 * riB1);
    }

    grid_barrier();

    // ===== Phase 2: losses. All scaled norms^2 == 9; bias = 18 =================
    float myLoss = 0.f;
    int   myCnt  = 0;

    if (b == 0) {
        // real-sample loss: one thread per row i.  d_c = 18 - 2*ip_c
        int i = tid;
        int ti = T[i];
        const float tl = 2.0f * LOG2E;
        const float nb = -18.0f * LOG2E;
        float s = 0.f;
        float pre[10];
        #pragma unroll
        for (int u = 0; u < 10; u++) pre[u] = g_Out[u * Nn + i];
        for (int cb = 0; cb < Cc; cb += 10) {
            float cur[10];
            #pragma unroll
            for (int u = 0; u < 10; u++) cur[u] = pre[u];
            if (cb < 90) {
                #pragma unroll
                for (int u = 0; u < 10; u++) pre[u] = g_Out[(cb + 10 + u) * Nn + i];
            }
            #pragma unroll
            for (int u = 0; u < 10; u++)
                s += ex2f(fmaf(tl, cur[u], nb));
        }
        float dT = fmaxf(fmaf(-2.f, g_Out[ti * Nn + i], 18.0f), 0.f);
        myLoss = dT + __logf(s);
    } else {
        // pair loss: block b handles i1 = b-1, pairs i2 = i1+1..255
        int i1 = b - 1;                 // 0..254
        int np = Nn - 1 - i1;           // 255..1
        if (tid < Cc) shIp1[tid] = g_Out[tid * Nn + i1];
        __syncthreads();
        if (tid < np) {
            int i2 = i1 + 1 + tid;
            int c1 = T[i1], c2 = T[i2];
            if (c1 != c2) {
                myCnt = 1;
                float x2p1i = g_Out[c1 * Nn + i2];
                float x2p2i = g_Out[c2 * Nn + i2];
                float x1p1 = clip1(shIp1[c1]);
                float x1p2 = clip1(shIp1[c2]);
                float x2p1 = clip1(x2p1i);
                float x2p2 = clip1(x2p2i);
                float num = x2p2 - x2p1;
                float den = num + x1p1 - x1p2;
                float lam = fminf(fmaxf(num / den, 0.3f), 0.7f);
                float lm  = 1.f - lam;

                float gg  = g_Out[(Cc + i1) * Nn + i2];     // Xn_i1 . Xn_i2
                float nw2 = 9.0f * (lam * lam + lm * lm) + 2.f * lam * lm * gg;
                float t2  = 6.0f / fmaxf(sqrtf(nw2), 1e-12f);   // 2*SCALE/||virt||
                float tl  = t2 * LOG2E;
                const float nb = -18.0f * LOG2E;

                // softmax denominator: s = sum_c exp2(tl*ip_c - 18*log2e)
                float s = 0.f;
                float pre[10];
                #pragma unroll
                for (int u = 0; u < 10; u++) pre[u] = g_Out[u * Nn + i2];
                for (int cb = 0; cb < Cc; cb += 10) {
                    float cur[10];
                    #pragma unroll
                    for (int u = 0; u < 10; u++) cur[u] = pre[u];
                    if (cb < 90) {
                        #pragma unroll
                        for (int u = 0; u < 10; u++) pre[u] = g_Out[(cb + 10 + u) * Nn + i2];
                    }
                    #pragma unroll
                    for (int u = 0; u < 10; u++) {
                        int c = cb + u;
                        float ip = fmaf(lam, shIp1[c] - cur[u], cur[u]);
                        s += ex2f(fmaf(tl, ip, nb));
                    }
                }
                float dc1 = fmaxf(fmaf(-t2, fmaf(lam, shIp1[c1] - x2p1i, x2p1i), 18.0f), 0.f);
                float dc2 = fmaxf(fmaf(-t2, fmaf(lam, shIp1[c2] - x2p2i, x2p2i), 18.0f), 0.f);
                myLoss = lam * dc1 + lm * dc2 + __logf(s);
            }
        }
    }

    // block reduce
    sred[tid]  = myLoss;
    sredi[tid] = myCnt;
    __syncthreads();
    for (int o = 128; o; o >>= 1) {
        if (tid < o) { sred[tid] += sred[tid + o]; sredi[tid] += sredi[tid + o]; }
        __syncthreads();
    }

    // ===== Phase 3: partial store + ticket; LAST block reduces in parallel =====
    if (tid == 0) {
        g_partF[b] = sred[0];
        g_partI[b] = sredi[0];
        __threadfence();
        unsigned t = atomicAdd(&g_done, 1u);
        lastFlag = (t == GB - 1);
    }
    __syncthreads();
    if (lastFlag) {
        sred[tid]  = __ldcg(&g_partF[tid]);    // bypass L1 (written by other SMs)
        sredi[tid] = __ldcg(&g_partI[tid]);
        __syncthreads();
        for (int o = 128; o; o >>= 1) {
            if (tid < o) { sred[tid] += sred[tid + o]; sredi[tid] += sredi[tid + o]; }
            __syncthreads();
        }
        if (tid == 0) {
            out[0] = sred[0] / (float)(Nn + sredi[0]);
            __threadfence();
            atomicExch(&g_done, 0u);           // reset for graph replay
        }
    }
}

// ---------------- entry -------------------------------------------------------
extern "C" void kernel_launch(void* const* d_in, const int* in_sizes, int n_in,
                              void* d_out, int out_size) {
    const float* X = (const float*)d_in[0];   // [256,512]
    const float* P = (const float*)d_in[1];   // [100,512]
    const int*   T = (const int*)d_in[2];     // [256]
    float* out = (float*)d_out;

    k_fused<<<GB, 256>>>(X, P, T, out);
}

// round 6
// speedup vs baseline: 1.8187x; 1.2527x over previous
#include <cuda_runtime.h>
#include <math.h>

#define Nn 256
#define Cc 100
#define Dd 512
#define RW (Nn + Cc)      // 356 rows (proxies first, then X)
#define GB 256            // grid; 2 CTAs/SM co-resident
#define RPAD 384          // padded rows in partial buffers
#define LOG2E 1.442695040888963f

// ---------------- scratch (device globals; no allocation allowed) -------------
__device__ float  g_part[4][RPAD * Nn]; // raw split-K partials
__device__ float  g_rinv[RW];           // 1/max(||row||,eps)
__device__ float  g_Out[RW * Nn];       // scaled: rows 0..99 IPt[c][i]; 100..355 G[i][j]
__device__ float  g_partF[GB];
__device__ int    g_partI[GB];
__device__ unsigned g_barCount = 0;
__device__ unsigned g_barGen   = 0;
__device__ unsigned g_done     = 0;

__device__ __forceinline__ float ex2f(float x) {
    float r; asm("ex2.approx.ftz.f32 %0, %1;" : "=f"(r) : "f"(x)); return r;
}

// ---------------- software grid barrier (all GB blocks co-resident) ----------
__device__ __forceinline__ void grid_barrier() {
    __syncthreads();
    __threadfence();
    if (threadIdx.x == 0) {
        unsigned oldgen = *(volatile unsigned*)&g_barGen;
        unsigned ticket = atomicAdd(&g_barCount, 1u);
        if (ticket == GB - 1) {
            g_barCount = 0;
            __threadfence();
            atomicExch(&g_barGen, oldgen + 1u);
        } else {
            while (*(volatile unsigned*)&g_barGen == oldgen) { __nanosleep(64); }
        }
        __threadfence();
    }
    __syncthreads();
}

__device__ __forceinline__ float clip1(float x) { return fminf(fmaxf(x, -1.f), 1.f); }

// ---------------- fused kernel ------------------------------------------------
__global__ void __launch_bounds__(256, 2)
k_fused(const float* __restrict__ X, const float* __restrict__ P,
        const int* __restrict__ T, float* __restrict__ out) {
    int tid  = threadIdx.x;    // 256
    int b    = blockIdx.x;     // 0..255
    int lane = tid & 31;
    int wid  = tid >> 5;       // 0..7

    __shared__ float As[32][66];     // transposed: As[kk][row], pitch 66 (8B-aligned)
    __shared__ float Bs[32][66];
    __shared__ float shIp1[Cc];
    __shared__ float sred[256];
    __shared__ int   sredi[256];
    __shared__ int   lastFlag;

    // ===== Phase 1a: split-K GEMM, RAW inputs (blocks 0..95) ====================
    // 24 tiles (64x64) x 4 K-slices of 128.  part[ks][r][j] = W_r[Ks].X_j[Ks]
    if (b < 96) {
        int ks = b & 3;
        int t  = b >> 2;
        int trow = (t % 6) * 64;
        int tcol = (t / 6) * 64;
        int kb   = ks * 128;

        int rowL = tid >> 2;           // 0..63 (load row)
        int kq   = tid & 3;            // 0..3
        int sb   = kq * 8;             // kk base within chunk
        int ga   = trow + rowL;
        const float* Arow = (ga < Cc) ? (P + ga * Dd)
                          : (ga < RW) ? (X + (ga - Cc) * Dd) : (const float*)0;
        const float* Brow = X + (tcol + rowL) * Dd;

        int ty = tid >> 4, tx = tid & 15;   // compute coords: rows 4ty.., cols 4tx..

        float acc[4][4];
        #pragma unroll
        for (int i = 0; i < 4; i++)
            #pragma unroll
            for (int j = 0; j < 4; j++) acc[i][j] = 0.f;

        float4 pa0, pa1, pb0, pb1;
        {
            int k0 = kb + sb;
            pa0 = Arow ? *(const float4*)(Arow + k0)     : make_float4(0,0,0,0);
            pa1 = Arow ? *(const float4*)(Arow + k0 + 4) : make_float4(0,0,0,0);
            pb0 = *(const float4*)(Brow + k0);
            pb1 = *(const float4*)(Brow + k0 + 4);
        }

        for (int ch = 0; ch < 4; ch++) {
            // store prefetched chunk (transposed)
            As[sb+0][rowL]=pa0.x; As[sb+1][rowL]=pa0.y; As[sb+2][rowL]=pa0.z; As[sb+3][rowL]=pa0.w;
            As[sb+4][rowL]=pa1.x; As[sb+5][rowL]=pa1.y; As[sb+6][rowL]=pa1.z; As[sb+7][rowL]=pa1.w;
            Bs[sb+0][rowL]=pb0.x; Bs[sb+1][rowL]=pb0.y; Bs[sb+2][rowL]=pb0.z; Bs[sb+3][rowL]=pb0.w;
            Bs[sb+4][rowL]=pb1.x; Bs[sb+5][rowL]=pb1.y; Bs[sb+6][rowL]=pb1.z; Bs[sb+7][rowL]=pb1.w;
            __syncthreads();

            if (ch < 3) {
                int k0 = kb + (ch + 1) * 32 + sb;
                pa0 = Arow ? *(const float4*)(Arow + k0)     : make_float4(0,0,0,0);
                pa1 = Arow ? *(const float4*)(Arow + k0 + 4) : make_float4(0,0,0,0);
                pb0 = *(const float4*)(Brow + k0);
                pb1 = *(const float4*)(Brow + k0 + 4);
            }

            #pragma unroll
            for (int kk = 0; kk < 32; kk++) {
                float2 a0 = *(const float2*)&As[kk][4 * ty];
                float2 a1 = *(const float2*)&As[kk][4 * ty + 2];
                float2 b0 = *(const float2*)&Bs[kk][4 * tx];
                float2 b1 = *(const float2*)&Bs[kk][4 * tx + 2];
                float av[4] = {a0.x, a0.y, a1.x, a1.y};
                float bv[4] = {b0.x, b0.y, b1.x, b1.y};
                #pragma unroll
                for (int i = 0; i < 4; i++)
                    #pragma unroll
                    for (int j = 0; j < 4; j++)
                        acc[i][j] = fmaf(av[i], bv[j], acc[i][j]);
            }
            __syncthreads();
        }

        // raw store to partial buffer (padded rows fine)
        float* Pt = g_part[ks];
        #pragma unroll
        for (int i = 0; i < 4; i++) {
            int r = trow + 4 * ty + i;
            *(float4*)&Pt[r * Nn + tcol + 4 * tx] =
                make_float4(acc[i][0], acc[i][1], acc[i][2], acc[i][3]);
        }
    }
    // ===== Phase 1b: row norms (blocks 96..140, concurrent with GEMM) ==========
    else if (b < 141) {
        int row = (b - 96) * 8 + wid;            // 45 blocks x 8 warps = 360 >= 356
        if (row < RW) {
            const float* rp = (row < Cc) ? (P + row * Dd) : (X + (row - Cc) * Dd);
            const float4* rp4 = (const float4*)rp;
            float s = 0.f;
            #pragma unroll
            for (int m = 0; m < 4; m++) {
                float4 v = rp4[lane + 32 * m];
                s += v.x * v.x + v.y * v.y + v.z * v.z + v.w * v.w;
            }
            #pragma unroll
            for (int o = 16; o; o >>= 1) s += __shfl_xor_sync(0xffffffffu, s, o);
            if (lane == 0) g_rinv[row] = 1.0f / fmaxf(sqrtf(s), 1e-12f);
        }
    }

    grid_barrier();

    // ===== Phase 2: reduce 4 partials + scale -> g_Out ==========================
    {
        int idx4 = b * 256 + tid;                 // float4 index
        if (idx4 < RW * (Nn / 4)) {
            int r  = idx4 >> 6;                   // row
            int c4 = idx4 & 63;                   // float4-col
            int o  = r * (Nn / 4) + c4;
            float4 s0 = ((const float4*)g_part[0])[o];
            float4 s1 = ((const float4*)g_part[1])[o];
            float4 s2 = ((const float4*)g_part[2])[o];
            float4 s3 = ((const float4*)g_part[3])[o];
            float sc = 9.0f * g_rinv[r];
            int cb = 4 * c4;
            float4 ov;
            ov.x = (s0.x + s1.x + s2.x + s3.x) * sc * g_rinv[Cc + cb];
            ov.y = (s0.y + s1.y + s2.y + s3.y) * sc * g_rinv[Cc + cb + 1];
            ov.z = (s0.z + s1.z + s2.z + s3.z) * sc * g_rinv[Cc + cb + 2];
            ov.w = (s0.w + s1.w + s2.w + s3.w) * sc * g_rinv[Cc + cb + 3];
            ((float4*)g_Out)[o] = ov;
        }
    }

    grid_barrier();

    // ===== Phase 3: losses. Scaled norms^2 == 9; bias = 18 ======================
    float myLoss = 0.f;
    int   myCnt  = 0;

    if (b == 0) {
        // real-sample loss: one thread per row i.  d_c = 18 - 2*ip_c
        int i = tid;
        int ti = T[i];
        const float tl = 2.0f * LOG2E;
        const float nb = -18.0f * LOG2E;
        float s = 0.f;
        float pre[10];
        #pragma unroll
        for (int u = 0; u < 10; u++) pre[u] = g_Out[u * Nn + i];
        for (int cb = 0; cb < Cc; cb += 10) {
            float cur[10];
            #pragma unroll
            for (int u = 0; u < 10; u++) cur[u] = pre[u];
            if (cb < 90) {
                #pragma unroll
                for (int u = 0; u < 10; u++) pre[u] = g_Out[(cb + 10 + u) * Nn + i];
            }
            #pragma unroll
            for (int u = 0; u < 10; u++)
                s += ex2f(fmaf(tl, cur[u], nb));
        }
        float dT = fmaxf(fmaf(-2.f, g_Out[ti * Nn + i], 18.0f), 0.f);
        myLoss = dT + __logf(s);
    } else {
        // pair loss: block b handles i1 = b-1, pairs i2 = i1+1..255
        int i1 = b - 1;
        int np = Nn - 1 - i1;
        if (tid < Cc) shIp1[tid] = g_Out[tid * Nn + i1];
        __syncthreads();
        if (tid < np) {
            int i2 = i1 + 1 + tid;
            int c1 = T[i1], c2 = T[i2];
            if (c1 != c2) {
                myCnt = 1;
                float x2p1i = g_Out[c1 * Nn + i2];
                float x2p2i = g_Out[c2 * Nn + i2];
                float x1p1 = clip1(shIp1[c1]);
                float x1p2 = clip1(shIp1[c2]);
                float x2p1 = clip1(x2p1i);
                float x2p2 = clip1(x2p2i);
                float num = x2p2 - x2p1;
                float den = num + x1p1 - x1p2;
                float lam = fminf(fmaxf(num / den, 0.3f), 0.7f);
                float lm  = 1.f - lam;

                float gg  = g_Out[(Cc + i1) * Nn + i2];
                float nw2 = 9.0f * (lam * lam + lm * lm) + 2.f * lam * lm * gg;
                float t2  = 6.0f / fmaxf(sqrtf(nw2), 1e-12f);
                float tl  = t2 * LOG2E;
                const float nb = -18.0f * LOG2E;

                float s = 0.f;
                float pre[10];
                #pragma unroll
                for (int u = 0; u < 10; u++) pre[u] = g_Out[u * Nn + i2];
                for (int cb = 0; cb < Cc; cb += 10) {
                    float cur[10];
                    #pragma unroll
                    for (int u = 0; u < 10; u++) cur[u] = pre[u];
                    if (cb < 90) {
                        #pragma unroll
                        for (int u = 0; u < 10; u++) pre[u] = g_Out[(cb + 10 + u) * Nn + i2];
                    }
                    #pragma unroll
                    for (int u = 0; u < 10; u++) {
                        int c = cb + u;
                        float ip = fmaf(lam, shIp1[c] - cur[u], cur[u]);
                        s += ex2f(fmaf(tl, ip, nb));
                    }
                }
                float dc1 = fmaxf(fmaf(-t2, fmaf(lam, shIp1[c1] - x2p1i, x2p1i), 18.0f), 0.f);
                float dc2 = fmaxf(fmaf(-t2, fmaf(lam, shIp1[c2] - x2p2i, x2p2i), 18.0f), 0.f);
                myLoss = lam * dc1 + lm * dc2 + __logf(s);
            }
        }
    }

    // block reduce
    sred[tid]  = myLoss;
    sredi[tid] = myCnt;
    __syncthreads();
    for (int o = 128; o; o >>= 1) {
        if (tid < o) { sred[tid] += sred[tid + o]; sredi[tid] += sredi[tid + o]; }
        __syncthreads();
    }

    // ===== Phase 4: partial store + ticket; last block reduces in parallel =====
    if (tid == 0) {
        g_partF[b] = sred[0];
        g_partI[b] = sredi[0];
        __threadfence();
        unsigned t = atomicAdd(&g_done, 1u);
        lastFlag = (t == GB - 1);
    }
    __syncthreads();
    if (lastFlag) {
        sred[tid]  = __ldcg(&g_partF[tid]);
        sredi[tid] = __ldcg(&g_partI[tid]);
        __syncthreads();
        for (int o = 128; o; o >>= 1) {
            if (tid < o) { sred[tid] += sred[tid + o]; sredi[tid] += sredi[tid + o]; }
            __syncthreads();
        }
        if (tid == 0) {
            out[0] = sred[0] / (float)(Nn + sredi[0]);
            __threadfence();
            atomicExch(&g_done, 0u);              // reset for graph replay
        }
    }
}

// ---------------- entry -------------------------------------------------------
extern "C" void kernel_launch(void* const* d_in, const int* in_sizes, int n_in,
                              void* d_out, int out_size) {
    const float* X = (const float*)d_in[0];   // [256,512]
    const float* P = (const float*)d_in[1];   // [100,512]
    const int*   T = (const int*)d_in[2];     // [256]
    float* out = (float*)d_out;

    k_fused<<<GB, 256>>>(X, P, T, out);
}

// round 7
// speedup vs baseline: 2.0183x; 1.1098x over previous
#include <cuda_runtime.h>
#include <math.h>

#define Nn 256
#define Cc 100
#define Dd 512
#define RW (Nn + Cc)      // 356 rows (proxies first, then X)
#define GB 256            // grid; 2 CTAs/SM co-resident
#define RPAD 384          // padded rows in partial buffers
#define NT 18             // GEMM output tiles after symmetry pruning
#define SK 8              // split-K factor (K-slice = 64)
#define LOG2E 1.442695040888963f

// 18 needed 64x64 tiles of the [384,256] output (rows: 100 IP + 256 G):
// lower-triangle G tiles that the loss never reads are skipped.
__constant__ unsigned char c_tr[NT] = {0,0,0,0, 1,1,1,1, 2,2,2,2, 3,3,3, 4,4, 5};
__constant__ unsigned char c_tc[NT] = {0,1,2,3, 0,1,2,3, 0,1,2,3, 1,2,3, 2,3, 3};

// ---------------- scratch (device globals; no allocation allowed) -------------
__device__ float  g_part[SK][RPAD * Nn]; // raw split-K partials (unwritten tiles stay 0)
__device__ float  g_rinv[RW];            // 1/max(||row||,eps)
__device__ float  g_Out[RW * Nn];        // scaled: rows 0..99 IPt[c][i]; 100..355 G[i][j]
__device__ float  g_partF[GB];
__device__ int    g_partI[GB];
__device__ unsigned g_barCount = 0;
__device__ unsigned g_barGen   = 0;
__device__ unsigned g_done     = 0;

__device__ __forceinline__ float ex2f(float x) {
    float r; asm("ex2.approx.ftz.f32 %0, %1;" : "=f"(r) : "f"(x)); return r;
}

// ---------------- software grid barrier (all GB blocks co-resident) ----------
__device__ __forceinline__ void grid_barrier() {
    __syncthreads();
    __threadfence();
    if (threadIdx.x == 0) {
        unsigned oldgen = *(volatile unsigned*)&g_barGen;
        unsigned ticket = atomicAdd(&g_barCount, 1u);
        if (ticket == GB - 1) {
            g_barCount = 0;
            __threadfence();
            atomicExch(&g_barGen, oldgen + 1u);
        } else {
            while (*(volatile unsigned*)&g_barGen == oldgen) { __nanosleep(64); }
        }
        __threadfence();
    }
    __syncthreads();
}

__device__ __forceinline__ float clip1(float x) { return fminf(fmaxf(x, -1.f), 1.f); }

// ---------------- fused kernel ------------------------------------------------
__global__ void __launch_bounds__(256, 2)
k_fused(const float* __restrict__ X, const float* __restrict__ P,
        const int* __restrict__ T, float* __restrict__ out) {
    int tid  = threadIdx.x;    // 256
    int b    = blockIdx.x;     // 0..255
    int lane = tid & 31;
    int wid  = tid >> 5;       // 0..7

    __shared__ float As[32][66];     // transposed: As[kk][row], pitch 66 (8B-aligned)
    __shared__ float Bs[32][66];
    __shared__ float shIp1[Cc];
    __shared__ float sred[256];
    __shared__ int   sredi[256];
    __shared__ int   lastFlag;

    // ===== Phase 1a: split-K GEMM, RAW inputs (blocks 0..143) ===================
    // 18 tiles (64x64) x 8 K-slices of 64.  part[ks][r][j] = W_r[Ks].X_j[Ks]
    if (b < NT * SK) {
        int ks = b & 7;
        int t  = b >> 3;
        int trow = c_tr[t] * 64;
        int tcol = c_tc[t] * 64;
        int kb   = ks * 64;

        int rowL = tid >> 2;           // 0..63 (load row)
        int kq   = tid & 3;            // 0..3
        int sb   = kq * 8;             // kk base within chunk
        int ga   = trow + rowL;
        const float* Arow = (ga < Cc) ? (P + ga * Dd)
                          : (ga < RW) ? (X + (ga - Cc) * Dd) : (const float*)0;
        const float* Brow = X + (tcol + rowL) * Dd;

        int ty = tid >> 4, tx = tid & 15;   // compute coords: rows 4ty.., cols 4tx..

        float acc[4][4];
        #pragma unroll
        for (int i = 0; i < 4; i++)
            #pragma unroll
            for (int j = 0; j < 4; j++) acc[i][j] = 0.f;

        float4 pa0, pa1, pb0, pb1;
        {
            int k0 = kb + sb;
            pa0 = Arow ? *(const float4*)(Arow + k0)     : make_float4(0,0,0,0);
            pa1 = Arow ? *(const float4*)(Arow + k0 + 4) : make_float4(0,0,0,0);
            pb0 = *(const float4*)(Brow + k0);
            pb1 = *(const float4*)(Brow + k0 + 4);
        }

        #pragma unroll
        for (int ch = 0; ch < 2; ch++) {
            // store prefetched chunk (transposed)
            As[sb+0][rowL]=pa0.x; As[sb+1][rowL]=pa0.y; As[sb+2][rowL]=pa0.z; As[sb+3][rowL]=pa0.w;
            As[sb+4][rowL]=pa1.x; As[sb+5][rowL]=pa1.y; As[sb+6][rowL]=pa1.z; As[sb+7][rowL]=pa1.w;
            Bs[sb+0][rowL]=pb0.x; Bs[sb+1][rowL]=pb0.y; Bs[sb+2][rowL]=pb0.z; Bs[sb+3][rowL]=pb0.w;
            Bs[sb+4][rowL]=pb1.x; Bs[sb+5][rowL]=pb1.y; Bs[sb+6][rowL]=pb1.z; Bs[sb+7][rowL]=pb1.w;
            __syncthreads();

            if (ch < 1) {
                int k0 = kb + 32 + sb;
                pa0 = Arow ? *(const float4*)(Arow + k0)     : make_float4(0,0,0,0);
                pa1 = Arow ? *(const float4*)(Arow + k0 + 4) : make_float4(0,0,0,0);
                pb0 = *(const float4*)(Brow + k0);
                pb1 = *(const float4*)(Brow + k0 + 4);
            }

            #pragma unroll
            for (int kk = 0; kk < 32; kk++) {
                float2 a0 = *(const float2*)&As[kk][4 * ty];
                float2 a1 = *(const float2*)&As[kk][4 * ty + 2];
                float2 b0 = *(const float2*)&Bs[kk][4 * tx];
                float2 b1 = *(const float2*)&Bs[kk][4 * tx + 2];
                float av[4] = {a0.x, a0.y, a1.x, a1.y};
                float bv[4] = {b0.x, b0.y, b1.x, b1.y};
                #pragma unroll
                for (int i = 0; i < 4; i++)
                    #pragma unroll
                    for (int j = 0; j < 4; j++)
                        acc[i][j] = fmaf(av[i], bv[j], acc[i][j]);
            }
            __syncthreads();
        }

        // raw store to partial buffer
        float* Pt = g_part[ks];
        #pragma unroll
        for (int i = 0; i < 4; i++) {
            int r = trow + 4 * ty + i;
            *(float4*)&Pt[r * Nn + tcol + 4 * tx] =
                make_float4(acc[i][0], acc[i][1], acc[i][2], acc[i][3]);
        }
    }
    // ===== Phase 1b: row norms (blocks 144..188, concurrent with GEMM) =========
    else if (b < 189) {
        int row = (b - 144) * 8 + wid;           // 45 blocks x 8 warps = 360 >= 356
        if (row < RW) {
            const float* rp = (row < Cc) ? (P + row * Dd) : (X + (row - Cc) * Dd);
            const float4* rp4 = (const float4*)rp;
            float s = 0.f;
            #pragma unroll
            for (int m = 0; m < 4; m++) {
                float4 v = rp4[lane + 32 * m];
                s += v.x * v.x + v.y * v.y + v.z * v.z + v.w * v.w;
            }
            #pragma unroll
            for (int o = 16; o; o >>= 1) s += __shfl_xor_sync(0xffffffffu, s, o);
            if (lane == 0) g_rinv[row] = 1.0f / fmaxf(sqrtf(s), 1e-12f);
        }
    }

    grid_barrier();

    // ===== Phase 2: reduce 8 partials + scale -> g_Out ==========================
    {
        int idx4 = b * 256 + tid;                 // float4 index
        if (idx4 < RW * (Nn / 4)) {
            int r  = idx4 >> 6;                   // row
            int c4 = idx4 & 63;                   // float4-col
            int o  = r * (Nn / 4) + c4;
            float4 sv = make_float4(0.f, 0.f, 0.f, 0.f);
            #pragma unroll
            for (int q = 0; q < SK; q++) {
                float4 sq = ((const float4*)g_part[q])[o];
                sv.x += sq.x; sv.y += sq.y; sv.z += sq.z; sv.w += sq.w;
            }
            float sc = 9.0f * g_rinv[r];
            int cb = 4 * c4;
            float4 ov;
            ov.x = sv.x * sc * g_rinv[Cc + cb];
            ov.y = sv.y * sc * g_rinv[Cc + cb + 1];
            ov.z = sv.z * sc * g_rinv[Cc + cb + 2];
            ov.w = sv.w * sc * g_rinv[Cc + cb + 3];
            ((float4*)g_Out)[o] = ov;
        }
    }

    grid_barrier();

    // ===== Phase 3: losses. Scaled norms^2 == 9; bias = 18 ======================
    float myLoss = 0.f;
    int   myCnt  = 0;

    if (b == 0) {
        // real-sample loss: one thread per row i.  d_c = 18 - 2*ip_c
        int i = tid;
        int ti = T[i];
        const float tl = 2.0f * LOG2E;
        const float nb = -18.0f * LOG2E;
        float s = 0.f;
        float pre[10];
        #pragma unroll
        for (int u = 0; u < 10; u++) pre[u] = g_Out[u * Nn + i];
        for (int cb = 0; cb < Cc; cb += 10) {
            float cur[10];
            #pragma unroll
            for (int u = 0; u < 10; u++) cur[u] = pre[u];
            if (cb < 90) {
                #pragma unroll
                for (int u = 0; u < 10; u++) pre[u] = g_Out[(cb + 10 + u) * Nn + i];
            }
            #pragma unroll
            for (int u = 0; u < 10; u++)
                s += ex2f(fmaf(tl, cur[u], nb));
        }
        float dT = fmaxf(fmaf(-2.f, g_Out[ti * Nn + i], 18.0f), 0.f);
        myLoss = dT + __logf(s);
    } else {
        // pair loss: block b handles i1 = b-1, pairs i2 = i1+1..255
        int i1 = b - 1;
        int np = Nn - 1 - i1;
        if (tid < Cc) shIp1[tid] = g_Out[tid * Nn + i1];
        __syncthreads();
        if (tid < np) {
            int i2 = i1 + 1 + tid;
            int c1 = T[i1], c2 = T[i2];
            if (c1 != c2) {
                myCnt = 1;
                float x2p1i = g_Out[c1 * Nn + i2];
                float x2p2i = g_Out[c2 * Nn + i2];
                float x1p1 = clip1(shIp1[c1]);
                float x1p2 = clip1(shIp1[c2]);
                float x2p1 = clip1(x2p1i);
                float x2p2 = clip1(x2p2i);
                float num = x2p2 - x2p1;
                float den = num + x1p1 - x1p2;
                float lam = fminf(fmaxf(num / den, 0.3f), 0.7f);
                float lm  = 1.f - lam;

                float gg  = g_Out[(Cc + i1) * Nn + i2];   // upper-triangle G (computed)
                float nw2 = 9.0f * (lam * lam + lm * lm) + 2.f * lam * lm * gg;
                float t2  = 6.0f / fmaxf(sqrtf(nw2), 1e-12f);
                float tl  = t2 * LOG2E;
                const float nb = -18.0f * LOG2E;

                float s = 0.f;
                float pre[10];
                #pragma unroll
                for (int u = 0; u < 10; u++) pre[u] = g_Out[u * Nn + i2];
                for (int cb = 0; cb < Cc; cb += 10) {
                    float cur[10];
                    #pragma unroll
                    for (int u = 0; u < 10; u++) cur[u] = pre[u];
                    if (cb < 90) {
                        #pragma unroll
                        for (int u = 0; u < 10; u++) pre[u] = g_Out[(cb + 10 + u) * Nn + i2];
                    }
                    #pragma unroll
                    for (int u = 0; u < 10; u++) {
                        int c = cb + u;
                        float ip = fmaf(lam, shIp1[c] - cur[u], cur[u]);
                        s += ex2f(fmaf(tl, ip, nb));
                    }
                }
                float dc1 = fmaxf(fmaf(-t2, fmaf(lam, shIp1[c1] - x2p1i, x2p1i), 18.0f), 0.f);
                float dc2 = fmaxf(fmaf(-t2, fmaf(lam, shIp1[c2] - x2p2i, x2p2i), 18.0f), 0.f);
                myLoss = lam * dc1 + lm * dc2 + __logf(s);
            }
        }
    }

    // block reduce
    sred[tid]  = myLoss;
    sredi[tid] = myCnt;
    __syncthreads();
    for (int o = 128; o; o >>= 1) {
        if (tid < o) { sred[tid] += sred[tid + o]; sredi[tid] += sredi[tid + o]; }
        __syncthreads();
    }

    // ===== Phase 4: partial store + ticket; last block reduces in parallel =====
    if (tid == 0) {
        g_partF[b] = sred[0];
        g_partI[b] = sredi[0];
        __threadfence();
        unsigned t = atomicAdd(&g_done, 1u);
        lastFlag = (t == GB - 1);
    }
    __syncthreads();
    if (lastFlag) {
        sred[tid]  = __ldcg(&g_partF[tid]);
        sredi[tid] = __ldcg(&g_partI[tid]);
        __syncthreads();
        for (int o = 128; o; o >>= 1) {
            if (tid < o) { sred[tid] += sred[tid + o]; sredi[tid] += sredi[tid + o]; }
            __syncthreads();
        }
        if (tid == 0) {
            out[0] = sred[0] / (float)(Nn + sredi[0]);
            __threadfence();
            atomicExch(&g_done, 0u);              // reset for graph replay
        }
    }
}

// ---------------- entry -------------------------------------------------------
extern "C" void kernel_launch(void* const* d_in, const int* in_sizes, int n_in,
                              void* d_out, int out_size) {
    const float* X = (const float*)d_in[0];   // [256,512]
    const float* P = (const float*)d_in[1];   // [100,512]
    const int*   T = (const int*)d_in[2];     // [256]
    float* out = (float*)d_out;

    k_fused<<<GB, 256>>>(X, P, T, out);
}